// round 7
// baseline (speedup 1.0000x reference)
#include <cuda_runtime.h>
#include <cuda_fp16.h>
#include <cstdint>
#include <cstddef>

#define B_   128
#define S_   1024
#define IN_  256
#define H_   1024
#define G4_  4096
#define OUT_ 256
#define NC_  128     // CTAs (1/SM)
#define NSTG 6       // A pipeline stages (16KB each)
#define CHB  16384   // chunk: 128 rows x 64 cols fp16, SW128 image
#define NKC  20      // chunks per step: 4 x + 16 h

// ---------------- device globals -------------------------------------------
// g_x: [t][kc(4)][16KB swizzled]   g_h: [buf][kc(16)][16KB swizzled]
__device__ __align__(1024) char g_x [(size_t)S_*4*CHB];
__device__ __align__(1024) char g_h [2][16*CHB];
__device__ __align__(16)  __half g_WxT[(size_t)G4_*IN_];   // [n][k]
__device__ __align__(16)  __half g_WhT[(size_t)G4_*H_];    // [n][k]
__device__ unsigned g_cnt;

__device__ __host__ __forceinline__ int swz(int o){ return o ^ ((o >> 3) & 0x70); }

// ---------------- helpers ---------------------------------------------------
__device__ __forceinline__ void cp16(void* smem, const void* gmem){
    unsigned s = (unsigned)__cvta_generic_to_shared(smem);
    asm volatile("cp.async.cg.shared.global [%0], [%1], 16;\n" :: "r"(s), "l"(gmem));
}
__device__ __forceinline__ void cp_commit(){ asm volatile("cp.async.commit_group;\n"); }
template<int N> __device__ __forceinline__ void cp_wait(){ asm volatile("cp.async.wait_group %0;\n" :: "n"(N)); }

__device__ __forceinline__ void mbar_init(uint32_t mbar, uint32_t cnt){
    asm volatile("mbarrier.init.shared.b64 [%0], %1;\n" :: "r"(mbar), "r"(cnt) : "memory");
}
__device__ __forceinline__ void mbar_expect_tx(uint32_t mbar, uint32_t tx){
    asm volatile("mbarrier.arrive.expect_tx.shared.b64 _, [%0], %1;\n" :: "r"(mbar), "r"(tx) : "memory");
}
__device__ __forceinline__ void mbar_arrive(uint32_t mbar){
    asm volatile("mbarrier.arrive.shared.b64 _, [%0];\n" :: "r"(mbar) : "memory");
}
__device__ __forceinline__ void bulk_g2s(uint32_t sdst, const void* gsrc, uint32_t bytes, uint32_t mbar){
    asm volatile("cp.async.bulk.shared::cluster.global.mbarrier::complete_tx::bytes [%0], [%1], %2, [%3];\n"
                 :: "r"(sdst), "l"(gsrc), "r"(bytes), "r"(mbar) : "memory");
}
__device__ __forceinline__ void mbar_wait(uint32_t mbar, uint32_t parity){
    asm volatile(
        "{\n\t.reg .pred P1;\n\t"
        "LAB_W_%=:\n\t"
        "mbarrier.try_wait.parity.acquire.cta.shared::cta.b64 P1, [%0], %1;\n\t"
        "@P1 bra LAB_D_%=;\n\t"
        "bra LAB_W_%=;\n\t"
        "LAB_D_%=:\n\t}"
        :: "r"(mbar), "r"(parity) : "memory");
}
__device__ __forceinline__ void mma16816(float* c, uint32_t a0, uint32_t a1, uint32_t a2, uint32_t a3,
                                         uint32_t b0, uint32_t b1){
    asm volatile(
        "mma.sync.aligned.m16n8k16.row.col.f32.f16.f16.f32 "
        "{%0,%1,%2,%3}, {%4,%5,%6,%7}, {%8,%9}, {%0,%1,%2,%3};\n"
        : "+f"(c[0]), "+f"(c[1]), "+f"(c[2]), "+f"(c[3])
        : "r"(a0), "r"(a1), "r"(a2), "r"(a3), "r"(b0), "r"(b1));
}
__device__ __forceinline__ float sigm_(float x){ return 1.f / (1.f + __expf(-x)); }
__device__ __forceinline__ float tanh_(float x){ return 2.f / (1.f + __expf(-2.f*x)) - 1.f; }

// ---------------- phase 0: converts ----------------------------------------
__global__ void conv_x_kernel(const float* __restrict__ x){
    size_t n = (size_t)B_*S_*IN_;
    for (size_t i = (size_t)blockIdx.x*blockDim.x + threadIdx.x; i < n; i += (size_t)gridDim.x*blockDim.x){
        int k  = (int)(i % IN_);
        size_t bs = i / IN_;
        int s  = (int)(bs % S_);
        int b  = (int)(bs / S_);
        char* chunk = g_x + ((size_t)s*4 + (k >> 6))*CHB;
        int o = b*128 + (k & 63)*2;
        *(__half*)(chunk + swz(o)) = __float2half(x[i]);
    }
}
__global__ void conv_w_kernel(const float* __restrict__ Wx, const float* __restrict__ Wh){
    size_t n1 = (size_t)G4_*IN_, n2 = (size_t)G4_*H_;
    for (size_t i = (size_t)blockIdx.x*blockDim.x + threadIdx.x; i < n1 + n2; i += (size_t)gridDim.x*blockDim.x){
        if (i < n1){
            int n = (int)(i / IN_), k = (int)(i % IN_);
            g_WxT[i] = __float2half(Wx[(size_t)k*G4_ + n]);
        } else {
            size_t j = i - n1;
            int n = (int)(j / H_), k = (int)(j % H_);
            g_WhT[j] = __float2half(Wh[(size_t)k*G4_ + n]);
        }
    }
}
__global__ void zero_h_kernel(){
    size_t n = sizeof(g_h)/4;
    unsigned* p = (unsigned*)g_h;
    for (size_t i = (size_t)blockIdx.x*blockDim.x + threadIdx.x; i < n; i += (size_t)gridDim.x*blockDim.x)
        p[i] = 0u;
    if (blockIdx.x == 0 && threadIdx.x == 0) g_cnt = 0u;
}

// ---------------- recurrence: 4 compute warps + 1 producer warp ------------
// smem: A stages 6x16KB | Wh 32x(1024+8) fp16 | Wx 32x(256+8) fp16 | mbars
constexpr int LDW_ = H_  + 8;
constexpr int LDX_ = IN_ + 8;
constexpr int A_OFF  = 0;
constexpr int WH_OFF = NSTG*CHB;                 // 98304
constexpr int WX_OFF = WH_OFF + 32*LDW_*2;       // 164352
constexpr int MB_OFF = WX_OFF + 32*LDX_*2;       // 181248
constexpr int SMEM_REC = MB_OFF + 12*8 + 32;     // full[6], empty[6]

__global__ __launch_bounds__(160,1) void lstm_rec_kernel(const float* __restrict__ bias){
    extern __shared__ __align__(16) char sh[];
    int tid = threadIdx.x, lane = tid & 31, w = tid >> 5;
    int gid = lane >> 2, ctid = lane & 3;
    int j0 = blockIdx.x * 8;

    uint32_t a_smem  = (uint32_t)__cvta_generic_to_shared(sh + A_OFF);
    uint32_t mb_full = (uint32_t)__cvta_generic_to_shared(sh + MB_OFF);       // +8*i
    uint32_t mb_emp  = mb_full + NSTG*8;                                      // +8*i
    __half* Whs = (__half*)(sh + WH_OFF);
    __half* Wxs = (__half*)(sh + WX_OFF);

    if (tid == 0){
        for (int i = 0; i < NSTG; i++){ mbar_init(mb_full + i*8, 1); mbar_init(mb_emp + i*8, 4); }
        asm volatile("fence.proxy.async.shared::cta;\n" ::: "memory");
    }
    // weight slices (padded, conflict-free for B LDS)
    for (int idx = tid; idx < 32*128; idx += 160){
        int r = idx >> 7, seg = idx & 127;
        cp16(&Whs[r*LDW_ + seg*8], g_WhT + ((size_t)((r>>3)*H_ + j0 + (r&7)))*H_ + seg*8);
    }
    for (int idx = tid; idx < 32*32; idx += 160){
        int r = idx >> 5, seg = idx & 31;
        cp16(&Wxs[r*LDX_ + seg*8], g_WxT + ((size_t)((r>>3)*H_ + j0 + (r&7)))*IN_ + seg*8);
    }
    cp_commit(); cp_wait<0>();
    __syncthreads();   // the ONLY full-block sync

    if (w == 4){
        // ----------------- producer warp (lane 0 only) -----------------
        if (lane == 0){
            int pst = 0, pwrap = 0;
            for (int t = 0; t < S_; t++){
                for (int kc = 0; kc < NKC; kc++){
                    if (kc == 4 && t > 0){
                        unsigned v;
                        do { asm volatile("ld.acquire.gpu.global.u32 %0, [%1];\n" : "=r"(v) : "l"(&g_cnt) : "memory"); }
                        while (v < (unsigned)t * NC_);
                    }
                    const char* src = (kc < 4) ? g_x + ((size_t)t*4 + kc)*CHB
                                               : g_h[t & 1] + (kc - 4)*CHB;
                    if (pwrap > 0) mbar_wait(mb_emp + pst*8, (unsigned)((pwrap - 1) & 1));
                    mbar_expect_tx(mb_full + pst*8, CHB);
                    bulk_g2s(a_smem + pst*CHB, src, CHB, mb_full + pst*8);
                    if (++pst == NSTG){ pst = 0; pwrap++; }
                }
            }
        }
        return;
    }

    // ----------------- compute warps (w = 0..3, 32 batch rows each) --------
    float2 bf = *(const float2*)&bias[0*H_ + j0 + ctid*2];
    float2 bi = *(const float2*)&bias[1*H_ + j0 + ctid*2];
    float2 bg = *(const float2*)&bias[2*H_ + j0 + ctid*2];
    float2 bo = *(const float2*)&bias[3*H_ + j0 + ctid*2];

    float cst[8];                       // [mt*4 + rh*2 + ji]
    #pragma unroll
    for (int i = 0; i < 8; i++) cst[i] = 0.f;

    int cstg = 0, cwrap = 0;
    int mrow = w * 32;

    for (int t = 0; t < S_; t++){
        float acc[2][4][4];
        #pragma unroll
        for (int mt = 0; mt < 2; mt++)
            #pragma unroll
            for (int nt = 0; nt < 4; nt++){ acc[mt][nt][0]=0; acc[mt][nt][1]=0; acc[mt][nt][2]=0; acc[mt][nt][3]=0; }

        for (int kc = 0; kc < NKC; kc++){
            mbar_wait(mb_full + cstg*8, (unsigned)(cwrap & 1));
            const char* A = sh + A_OFF + cstg*CHB;
            const __half* Bb = (kc < 4) ? Wxs : Whs;
            int ldb   = (kc < 4) ? LDX_ : LDW_;
            int kbase = (kc < 4) ? kc*64 : (kc - 4)*64;
            #pragma unroll
            for (int kk = 0; kk < 64; kk += 16){
                uint32_t b0[4], b1[4];
                #pragma unroll
                for (int nt = 0; nt < 4; nt++){
                    const __half* wr = Bb + (nt*8 + gid)*ldb + kbase + kk + ctid*2;
                    b0[nt] = *(const uint32_t*)wr;
                    b1[nt] = *(const uint32_t*)(wr + 8);
                }
                #pragma unroll
                for (int mt = 0; mt < 2; mt++){
                    int r = mrow + mt*16 + gid;
                    int cb = (kk + ctid*2)*2;
                    uint32_t a0 = *(const uint32_t*)(A + swz( r     *128 + cb     ));
                    uint32_t a1 = *(const uint32_t*)(A + swz((r + 8)*128 + cb     ));
                    uint32_t a2 = *(const uint32_t*)(A + swz( r     *128 + cb + 16));
                    uint32_t a3 = *(const uint32_t*)(A + swz((r + 8)*128 + cb + 16));
                    #pragma unroll
                    for (int nt = 0; nt < 4; nt++)
                        mma16816(acc[mt][nt], a0, a1, a2, a3, b0[nt], b1[nt]);
                }
            }
            if (lane == 0) mbar_arrive(mb_emp + cstg*8);
            if (++cstg == NSTG){ cstg = 0; cwrap++; }
        }

        // epilogue: + bias -> activations -> c,h update (register-local)
        char* hdst = g_h[(t + 1) & 1] + (j0 >> 6)*CHB;
        #pragma unroll
        for (int mt = 0; mt < 2; mt++){
            #pragma unroll
            for (int rh = 0; rh < 2; rh++){
                int m = mrow + mt*16 + gid + rh*8;
                __half2 hv;
                #pragma unroll
                for (int ji = 0; ji < 2; ji++){
                    int c = rh*2 + ji, s = mt*4 + rh*2 + ji;
                    float fg = sigm_(acc[mt][0][c] + (ji ? bf.y : bf.x));
                    float ig = sigm_(acc[mt][1][c] + (ji ? bi.y : bi.x));
                    float gg = tanh_(acc[mt][2][c] + (ji ? bg.y : bg.x));
                    float og = sigm_(acc[mt][3][c] + (ji ? bo.y : bo.x));
                    float cn = fg*cst[s] + ig*gg;
                    cst[s] = cn;
                    float hn = og * tanh_(cn);
                    if (ji == 0) hv.x = __float2half(hn); else hv.y = __float2half(hn);
                }
                *(uint32_t*)(hdst + swz(m*128 + (j0 & 63)*2 + ctid*4)) = *(uint32_t*)&hv;
            }
        }

        asm volatile("bar.sync 1, 128;\n" ::: "memory");   // compute warps only
        if (tid == 0){
            __threadfence();
            asm volatile("red.release.gpu.global.add.u32 [%0], %1;\n" :: "l"(&g_cnt), "r"(1u) : "memory");
        }
    }
}

// ---------------- final FC: out = h_T @ Wfc + bfc (fp32) -------------------
__global__ __launch_bounds__(256) void fc_kernel(const float* __restrict__ Wfc,
                                                 const float* __restrict__ bfc,
                                                 float* __restrict__ out){
    __shared__ float hsm[H_];
    int b = blockIdx.x, o = threadIdx.x;
    for (int k = o; k < H_; k += 256){
        const char* chunk = g_h[0] + (k >> 6)*CHB;   // S even -> final h in buf 0
        hsm[k] = __half2float(*(const __half*)(chunk + swz(b*128 + (k & 63)*2)));
    }
    __syncthreads();
    float s = bfc[o];
    #pragma unroll 8
    for (int k = 0; k < H_; k++) s = fmaf(hsm[k], Wfc[(size_t)k*OUT_ + o], s);
    out[(size_t)b*OUT_ + o] = s;
}

// ---------------- entry -----------------------------------------------------
extern "C" void kernel_launch(void* const* d_in, const int* in_sizes, int n_in,
                              void* d_out, int out_size){
    (void)in_sizes; (void)n_in; (void)out_size;
    const float* x   = (const float*)d_in[0];
    const float* Wx  = (const float*)d_in[1];
    const float* Wh  = (const float*)d_in[2];
    const float* b   = (const float*)d_in[3];
    const float* Wfc = (const float*)d_in[4];
    const float* bfc = (const float*)d_in[5];
    float* out = (float*)d_out;

    cudaFuncSetAttribute(lstm_rec_kernel, cudaFuncAttributeMaxDynamicSharedMemorySize, SMEM_REC);

    conv_x_kernel<<<2048, 256>>>(x);
    conv_w_kernel<<<1024, 256>>>(Wx, Wh);
    zero_h_kernel<<<256, 256>>>();
    lstm_rec_kernel<<<NC_, 160, SMEM_REC>>>(b);
    fc_kernel<<<B_, 256>>>(Wfc, bfc, out);
}